// round 10
// baseline (speedup 1.0000x reference)
#include <cuda_runtime.h>

#define B   128
#define M   200
#define S   20
#define D   128
#define NC  10000
#define CL  10
#define HOPS 3

// Scratch (no cudaMalloc allowed)
__device__ float g_m[B * M * D];      // 13.1 MB: memory encodings
__device__ float g_u[B * D];          // query state (b-major, hops input)
__device__ float g_uT[D * B];         // query state transposed (gemm A operand)
__device__ float g_cand[NC * D];      // candidate sums

// ---------------------------------------------------------------------------
// packed f32x2 helpers
// ---------------------------------------------------------------------------
__device__ __forceinline__ unsigned long long pack2(float lo, float hi) {
    unsigned long long r;
    asm("mov.b64 %0, {%1, %2};" : "=l"(r) : "f"(lo), "f"(hi));
    return r;
}
__device__ __forceinline__ void unpack2(unsigned long long p, float& lo, float& hi) {
    asm("mov.b64 {%0, %1}, %2;" : "=f"(lo), "=f"(hi) : "l"(p));
}
__device__ __forceinline__ unsigned long long fma2(unsigned long long a,
                                                   unsigned long long b,
                                                   unsigned long long c) {
    unsigned long long d;
    asm("fma.rn.f32x2 %0, %1, %2, %3;" : "=l"(d) : "l"(a), "l"(b), "l"(c));
    return d;
}

// ---------------------------------------------------------------------------
// Gather primitives (R6 structure: warp per row, measured near LTS cap)
// ---------------------------------------------------------------------------
template <int N>
__device__ __forceinline__ void gather_row(const int* __restrict__ idxp,
                                           const float* __restrict__ tab,
                                           float* __restrict__ dst,
                                           int lane) {
    int myidx = (lane < N) ? idxp[lane] : 0;
    float4 acc = make_float4(0.f, 0.f, 0.f, 0.f);
#pragma unroll
    for (int s = 0; s < N; s++) {
        int idx = __shfl_sync(0xffffffffu, myidx, s);
        if (idx != 0) {
            float4 v = *(const float4*)(tab + (size_t)idx * D + lane * 4);
            acc.x += v.x; acc.y += v.y; acc.z += v.z; acc.w += v.w;
        }
    }
    *(float4*)(dst + lane * 4) = acc;
}

// Kernel 1a (main stream): story + query gathers (A table only)
#define SQ_ROWS (B * M + B)
__global__ void gather_sq_kernel(const int* __restrict__ stories,
                                 const int* __restrict__ queries,
                                 const float* __restrict__ A) {
    const int row  = (blockIdx.x * blockDim.x + threadIdx.x) >> 5;
    const int lane = threadIdx.x & 31;
    if (row >= SQ_ROWS) return;
    if (row < B * M) {
        gather_row<S>(stories + (size_t)row * S, A, g_m + (size_t)row * D, lane);
    } else {
        const int b = row - B * M;
        gather_row<S>(queries + (size_t)b * S, A, g_u + (size_t)b * D, lane);
    }
}

// Kernel 1b (side stream, overlapped with hops): candidate gather (W table)
__global__ void gather_cand_kernel(const int* __restrict__ candidates,
                                   const float* __restrict__ W) {
    const int row  = (blockIdx.x * blockDim.x + threadIdx.x) >> 5;
    const int lane = threadIdx.x & 31;
    if (row >= NC) return;
    gather_row<CL>(candidates + (size_t)row * CL, W, g_cand + (size_t)row * D, lane);
}

// ---------------------------------------------------------------------------
// Kernel 2: 3 attention hops; dot-phase u hoisted into registers.
// ---------------------------------------------------------------------------
#define HW_PITCH 129
#define HOP_THREADS 256

__global__ void hops_kernel(const float* __restrict__ Hw) {
    extern __shared__ float smem[];
    float* sm_m   = smem;                        // M*D
    float* sm_h   = sm_m + M * D;                // D*HW_PITCH
    float* sm_u   = sm_h + D * HW_PITCH;         // D
    float* sm_dot = sm_u + D;                    // M
    float* sm_po  = sm_dot + M;                  // 256 (o partials)
    float* sm_ph  = sm_po + HOP_THREADS;         // 256 (h partials)
    float* sm_red = sm_ph + HOP_THREADS;         // 16

    const int b  = blockIdx.x;
    const int t  = threadIdx.x;
    const int warp = t >> 5, lane = t & 31;

    {
        const float4* gm4 = (const float4*)(g_m + (size_t)b * M * D);
        float4* sm4 = (float4*)sm_m;
        for (int i = t; i < M * D / 4; i += HOP_THREADS) sm4[i] = gm4[i];
        for (int i = t; i < D * D; i += HOP_THREADS) {
            int d = i >> 7, k = i & 127;
            sm_h[d * HW_PITCH + k] = Hw[i];
        }
        if (t < D) sm_u[t] = g_u[b * D + t];
    }
    __syncthreads();

    for (int hop = 0; hop < HOPS; hop++) {
        // u cached in registers for the dot phase (halves dot-phase LDS)
        float ur[4];
#pragma unroll
        for (int i = 0; i < 4; i++) ur[i] = sm_u[lane + 32 * i];

        // ---- dotted[mm] = <m[mm], u> : warp per row
        for (int mm = warp; mm < M; mm += HOP_THREADS / 32) {
            const float* row = sm_m + mm * D;
            float s = 0.f;
#pragma unroll
            for (int i = 0; i < 4; i++) s += row[lane + 32 * i] * ur[i];
#pragma unroll
            for (int off = 16; off; off >>= 1)
                s += __shfl_xor_sync(0xffffffffu, s, off);
            if (lane == 0) sm_dot[mm] = s;
        }
        __syncthreads();

        // ---- softmax max (warp shuffle + cross-warp)
        float v = (t < M) ? sm_dot[t] : -1e30f;
#pragma unroll
        for (int off = 16; off; off >>= 1)
            v = fmaxf(v, __shfl_xor_sync(0xffffffffu, v, off));
        if (lane == 0) sm_red[warp] = v;
        __syncthreads();
        if (t == 0) {
            float mx = sm_red[0];
#pragma unroll
            for (int w = 1; w < 8; w++) mx = fmaxf(mx, sm_red[w]);
            sm_red[8] = mx;
        }
        __syncthreads();
        const float mx = sm_red[8];

        // ---- exp + sum
        float e = 0.f;
        if (t < M) { e = __expf(sm_dot[t] - mx); sm_dot[t] = e; }
        float sv = e;
#pragma unroll
        for (int off = 16; off; off >>= 1)
            sv += __shfl_xor_sync(0xffffffffu, sv, off);
        if (lane == 0) sm_red[warp] = sv;
        __syncthreads();
        if (t == 0) {
            float su = 0.f;
#pragma unroll
            for (int w = 0; w < 8; w++) su += sm_red[w];
            sm_red[9] = 1.f / su;
        }
        __syncthreads();
        const float inv = sm_red[9];

        // ---- o partial (half-block splits mm) + h partial (splits k)
        {
            const int half = t >> 7;
            const int d    = t & 127;
            float o = 0.f;
            const int m0 = half * (M / 2), m1 = m0 + (M / 2);
            for (int mm = m0; mm < m1; mm++)
                o += sm_dot[mm] * sm_m[mm * D + d];
            sm_po[t] = o;

            float h = 0.f;
            const int k0 = half * (D / 2), k1 = k0 + (D / 2);
            const float* hr = sm_h + d * HW_PITCH;
#pragma unroll 8
            for (int k = k0; k < k1; k++) h += hr[k] * sm_u[k];
            sm_ph[t] = h;
        }
        __syncthreads();

        if (t < D) {
            float o = (sm_po[t] + sm_po[t + 128]) * inv;
            float h = sm_ph[t] + sm_ph[t + 128];
            sm_u[t] = tanhf(h + o);
        }
        __syncthreads();
    }
    if (t < D) g_uT[t * B + b] = sm_u[t];   // transposed for GEMM A-stage
}

// ---------------------------------------------------------------------------
// Kernel 3: logits = u @ cand^T. Single wave (10000 = 125 x 80), 512 threads.
// Per-thread 4b x 5c via f32x2 FFMA2: A b-pairs loaded pre-packed as
// ulonglong2 (zero pack cost), cv duplicated into both halves.
// ---------------------------------------------------------------------------
#define CT   80            // c-tile width
#define SUP  132           // su pitch (b dim), mult of 4, not mult of 32
#define SCP  84            // sc pitch (c dim), mult of 4, not mult of 32
#define GT   512           // gemm threads

__global__ void gemm_kernel(float* __restrict__ out) {
    extern __shared__ float sm[];
    float* su = sm;              // su[k*SUP + b]
    float* sc = sm + D * SUP;    // sc[k*SCP + c]
    const int t = threadIdx.x;
    const int cbase = blockIdx.x * CT;

    for (int i = t; i < D * B; i += GT) {
        int k = i >> 7, b = i & 127;
        su[k * SUP + b] = g_uT[i];
    }
    for (int i = t; i < CT * D; i += GT) {
        int c = i >> 7, k = i & 127;
        sc[k * SCP + c] = g_cand[(size_t)(cbase + c) * D + k];
    }
    __syncthreads();

    const int tc = t & 15, tb = t >> 4;       // 32 b-groups x 16 c-groups
    const int b0 = tb * 4, c0 = tc * 5;
    unsigned long long acc[2][5] = {};        // b-pairs x c, packed f32x2

#pragma unroll 8
    for (int k = 0; k < D; k++) {
        ulonglong2 ap = *(const ulonglong2*)&su[k * SUP + b0];  // (b0,b1)(b2,b3)
        unsigned long long cvp[5];
#pragma unroll
        for (int j = 0; j < 5; j++) {
            float c = sc[k * SCP + c0 + j];
            cvp[j] = pack2(c, c);
        }
#pragma unroll
        for (int j = 0; j < 5; j++) {
            acc[0][j] = fma2(ap.x, cvp[j], acc[0][j]);
            acc[1][j] = fma2(ap.y, cvp[j], acc[1][j]);
        }
    }

#pragma unroll
    for (int p = 0; p < 2; p++) {
        float* r0 = out + (size_t)(b0 + 2 * p)     * NC + cbase + c0;
        float* r1 = out + (size_t)(b0 + 2 * p + 1) * NC + cbase + c0;
#pragma unroll
        for (int j = 0; j < 5; j++) {
            float lo, hi;
            unpack2(acc[p][j], lo, hi);
            r0[j] = lo;
            r1[j] = hi;
        }
    }
}

// ---------------------------------------------------------------------------
extern "C" void kernel_launch(void* const* d_in, const int* in_sizes, int n_in,
                              void* d_out, int out_size) {
    const int*   stories    = (const int*)d_in[0];
    const int*   queries    = (const int*)d_in[1];
    const int*   candidates = (const int*)d_in[2];
    const float* A_tab      = (const float*)d_in[3];
    const float* W_tab      = (const float*)d_in[4];
    const float* H_w        = (const float*)d_in[5];
    float*       out        = (float*)d_out;

    // host-side objects created once (no device allocations)
    static cudaStream_t s2 = nullptr;
    static cudaEvent_t  evFork = nullptr, evJoin = nullptr;
    if (s2 == nullptr) {
        cudaStreamCreateWithFlags(&s2, cudaStreamNonBlocking);
        cudaEventCreateWithFlags(&evFork, cudaEventDisableTiming);
        cudaEventCreateWithFlags(&evJoin, cudaEventDisableTiming);
    }

    const int hops_smem = (M * D + D * HW_PITCH + D + M + 2 * HOP_THREADS + 16) * sizeof(float);
    const int gemm_smem = (D * SUP + D * SCP) * sizeof(float);
    cudaFuncSetAttribute(hops_kernel, cudaFuncAttributeMaxDynamicSharedMemorySize, hops_smem);
    cudaFuncSetAttribute(gemm_kernel, cudaFuncAttributeMaxDynamicSharedMemorySize, gemm_smem);

    // fork: candidate gather runs on s2, overlapped with story-gather tail + hops
    cudaEventRecord(evFork, 0);
    cudaStreamWaitEvent(s2, evFork, 0);
    gather_cand_kernel<<<(NC + 7) / 8, 256, 0, s2>>>(candidates, W_tab);
    cudaEventRecord(evJoin, s2);

    // main chain
    gather_sq_kernel<<<(SQ_ROWS + 7) / 8, 256>>>(stories, queries, A_tab);
    hops_kernel<<<B, HOP_THREADS, hops_smem>>>(H_w);

    // join before gemm (needs g_cand + g_uT)
    cudaStreamWaitEvent(0, evJoin, 0);
    gemm_kernel<<<NC / CT, GT, gemm_smem>>>(out);
}

// round 12
// speedup vs baseline: 1.0885x; 1.0885x over previous
#include <cuda_runtime.h>

#define B   128
#define M   200
#define S   20
#define D   128
#define NC  10000
#define CL  10
#define HOPS 3

// Scratch (no cudaMalloc allowed)
__device__ float g_m[B * M * D];      // 13.1 MB: memory encodings
__device__ float g_u[B * D];          // query state (b-major, hops input)
__device__ float g_uT[D * B];         // query state transposed (gemm A operand)
__device__ float g_cand[NC * D];      // candidate sums

// ---------------------------------------------------------------------------
// Gather primitives (R6 structure: warp per row, measured near LTS cap)
// ---------------------------------------------------------------------------
template <int N>
__device__ __forceinline__ void gather_row(const int* __restrict__ idxp,
                                           const float* __restrict__ tab,
                                           float* __restrict__ dst,
                                           int lane) {
    int myidx = (lane < N) ? idxp[lane] : 0;
    float4 acc = make_float4(0.f, 0.f, 0.f, 0.f);
#pragma unroll
    for (int s = 0; s < N; s++) {
        int idx = __shfl_sync(0xffffffffu, myidx, s);
        if (idx != 0) {
            float4 v = *(const float4*)(tab + (size_t)idx * D + lane * 4);
            acc.x += v.x; acc.y += v.y; acc.z += v.z; acc.w += v.w;
        }
    }
    *(float4*)(dst + lane * 4) = acc;
}

// Kernel 1a (main stream): story + query gathers (A table only)
#define SQ_ROWS (B * M + B)
__global__ void gather_sq_kernel(const int* __restrict__ stories,
                                 const int* __restrict__ queries,
                                 const float* __restrict__ A) {
    const int row  = (blockIdx.x * blockDim.x + threadIdx.x) >> 5;
    const int lane = threadIdx.x & 31;
    if (row >= SQ_ROWS) return;
    if (row < B * M) {
        gather_row<S>(stories + (size_t)row * S, A, g_m + (size_t)row * D, lane);
    } else {
        const int b = row - B * M;
        gather_row<S>(queries + (size_t)b * S, A, g_u + (size_t)b * D, lane);
    }
}

// Kernel 1b (side stream, AFTER sq-gather, overlapped with hops)
__global__ void gather_cand_kernel(const int* __restrict__ candidates,
                                   const float* __restrict__ W) {
    const int row  = (blockIdx.x * blockDim.x + threadIdx.x) >> 5;
    const int lane = threadIdx.x & 31;
    if (row >= NC) return;
    gather_row<CL>(candidates + (size_t)row * CL, W, g_cand + (size_t)row * D, lane);
}

// ---------------------------------------------------------------------------
// Kernel 2: 3 attention hops (R10 version).
// ---------------------------------------------------------------------------
#define HW_PITCH 129
#define HOP_THREADS 256

__global__ void hops_kernel(const float* __restrict__ Hw) {
    extern __shared__ float smem[];
    float* sm_m   = smem;                        // M*D
    float* sm_h   = sm_m + M * D;                // D*HW_PITCH
    float* sm_u   = sm_h + D * HW_PITCH;         // D
    float* sm_dot = sm_u + D;                    // M
    float* sm_po  = sm_dot + M;                  // 256
    float* sm_ph  = sm_po + HOP_THREADS;         // 256
    float* sm_red = sm_ph + HOP_THREADS;         // 16

    const int b  = blockIdx.x;
    const int t  = threadIdx.x;
    const int warp = t >> 5, lane = t & 31;

    {
        const float4* gm4 = (const float4*)(g_m + (size_t)b * M * D);
        float4* sm4 = (float4*)sm_m;
        for (int i = t; i < M * D / 4; i += HOP_THREADS) sm4[i] = gm4[i];
        for (int i = t; i < D * D; i += HOP_THREADS) {
            int d = i >> 7, k = i & 127;
            sm_h[d * HW_PITCH + k] = Hw[i];
        }
        if (t < D) sm_u[t] = g_u[b * D + t];
    }
    __syncthreads();

    for (int hop = 0; hop < HOPS; hop++) {
        float ur[4];
#pragma unroll
        for (int i = 0; i < 4; i++) ur[i] = sm_u[lane + 32 * i];

        for (int mm = warp; mm < M; mm += HOP_THREADS / 32) {
            const float* row = sm_m + mm * D;
            float s = 0.f;
#pragma unroll
            for (int i = 0; i < 4; i++) s += row[lane + 32 * i] * ur[i];
#pragma unroll
            for (int off = 16; off; off >>= 1)
                s += __shfl_xor_sync(0xffffffffu, s, off);
            if (lane == 0) sm_dot[mm] = s;
        }
        __syncthreads();

        float v = (t < M) ? sm_dot[t] : -1e30f;
#pragma unroll
        for (int off = 16; off; off >>= 1)
            v = fmaxf(v, __shfl_xor_sync(0xffffffffu, v, off));
        if (lane == 0) sm_red[warp] = v;
        __syncthreads();
        if (t == 0) {
            float mx = sm_red[0];
#pragma unroll
            for (int w = 1; w < 8; w++) mx = fmaxf(mx, sm_red[w]);
            sm_red[8] = mx;
        }
        __syncthreads();
        const float mx = sm_red[8];

        float e = 0.f;
        if (t < M) { e = __expf(sm_dot[t] - mx); sm_dot[t] = e; }
        float sv = e;
#pragma unroll
        for (int off = 16; off; off >>= 1)
            sv += __shfl_xor_sync(0xffffffffu, sv, off);
        if (lane == 0) sm_red[warp] = sv;
        __syncthreads();
        if (t == 0) {
            float su = 0.f;
#pragma unroll
            for (int w = 0; w < 8; w++) su += sm_red[w];
            sm_red[9] = 1.f / su;
        }
        __syncthreads();
        const float inv = sm_red[9];

        {
            const int half = t >> 7;
            const int d    = t & 127;
            float o = 0.f;
            const int m0 = half * (M / 2), m1 = m0 + (M / 2);
            for (int mm = m0; mm < m1; mm++)
                o += sm_dot[mm] * sm_m[mm * D + d];
            sm_po[t] = o;

            float h = 0.f;
            const int k0 = half * (D / 2), k1 = k0 + (D / 2);
            const float* hr = sm_h + d * HW_PITCH;
#pragma unroll 8
            for (int k = k0; k < k1; k++) h += hr[k] * sm_u[k];
            sm_ph[t] = h;
        }
        __syncthreads();

        if (t < D) {
            float o = (sm_po[t] + sm_po[t + 128]) * inv;
            float h = sm_ph[t] + sm_ph[t + 128];
            sm_u[t] = tanhf(h + o);
        }
        __syncthreads();
    }
    if (t < D) g_uT[t * B + b] = sm_u[t];
}

// ---------------------------------------------------------------------------
// Kernel 3: logits = u @ cand^T. Single wave: 125 CTAs (10000 = 125 x 80),
// 640 threads (32 tb x 20 tc), per-thread 4b x 4c -> BOTH operands LDS.128.
// k unrolled x4 with loads hoisted (8 LDS.128 then 64 FFMA): deep MLP,
// no exposed LDS latency. Pitches in odd float4 units -> conflict-free.
// ---------------------------------------------------------------------------
#define CT   80                 // c-tile width
#define SUP  132                // su pitch floats (33 float4)
#define SCP  84                 // sc pitch floats (21 float4)
#define GT   640                // gemm threads (20 warps)

__global__ void __launch_bounds__(GT, 1) gemm_kernel(float* __restrict__ out) {
    extern __shared__ float sm[];
    float* su = sm;              // su[k*SUP + b], 128 b
    float* sc = sm + D * SUP;    // sc[k*SCP + c], 80 c
    const int t = threadIdx.x;
    const int cbase = blockIdx.x * CT;

    for (int i = t; i < D * B; i += GT) {
        int k = i >> 7, b = i & 127;
        su[k * SUP + b] = g_uT[i];
    }
    for (int i = t; i < CT * D; i += GT) {
        int c = i >> 7, k = i & 127;
        sc[k * SCP + c] = g_cand[(size_t)(cbase + c) * D + k];
    }
    __syncthreads();

    const int tc = t % 20, tb = t / 20;     // tb 0..31, tc 0..19
    const int b0 = tb * 4, c0 = tc * 4;
    float acc[4][4] = {};

#pragma unroll
    for (int k = 0; k < D; k += 4) {
        float4 a[4], c[4];
#pragma unroll
        for (int q = 0; q < 4; q++) {
            a[q] = *(const float4*)&su[(k + q) * SUP + b0];
            c[q] = *(const float4*)&sc[(k + q) * SCP + c0];
        }
#pragma unroll
        for (int q = 0; q < 4; q++) {
            float av[4] = {a[q].x, a[q].y, a[q].z, a[q].w};
            float cv[4] = {c[q].x, c[q].y, c[q].z, c[q].w};
#pragma unroll
            for (int i = 0; i < 4; i++)
#pragma unroll
                for (int j = 0; j < 4; j++) acc[i][j] += av[i] * cv[j];
        }
    }

#pragma unroll
    for (int i = 0; i < 4; i++) {
        *(float4*)&out[(size_t)(b0 + i) * NC + cbase + c0] =
            make_float4(acc[i][0], acc[i][1], acc[i][2], acc[i][3]);
    }
}

// ---------------------------------------------------------------------------
extern "C" void kernel_launch(void* const* d_in, const int* in_sizes, int n_in,
                              void* d_out, int out_size) {
    const int*   stories    = (const int*)d_in[0];
    const int*   queries    = (const int*)d_in[1];
    const int*   candidates = (const int*)d_in[2];
    const float* A_tab      = (const float*)d_in[3];
    const float* W_tab      = (const float*)d_in[4];
    const float* H_w        = (const float*)d_in[5];
    float*       out        = (float*)d_out;

    static cudaStream_t s2 = nullptr;
    static cudaEvent_t  evSq = nullptr, evJoin = nullptr;
    if (s2 == nullptr) {
        cudaStreamCreateWithFlags(&s2, cudaStreamNonBlocking);
        cudaEventCreateWithFlags(&evSq, cudaEventDisableTiming);
        cudaEventCreateWithFlags(&evJoin, cudaEventDisableTiming);
    }

    const int hops_smem = (M * D + D * HW_PITCH + D + M + 2 * HOP_THREADS + 16) * sizeof(float);
    const int gemm_smem = (D * SUP + D * SCP) * sizeof(float);   // ~110.6 KB
    cudaFuncSetAttribute(hops_kernel, cudaFuncAttributeMaxDynamicSharedMemorySize, hops_smem);
    cudaFuncSetAttribute(gemm_kernel, cudaFuncAttributeMaxDynamicSharedMemorySize, gemm_smem);

    // main: sq gather first (full LTS to itself)
    gather_sq_kernel<<<(SQ_ROWS + 7) / 8, 256>>>(stories, queries, A_tab);
    cudaEventRecord(evSq, 0);

    // side: cand gather AFTER sq gather, concurrent with hops
    cudaStreamWaitEvent(s2, evSq, 0);
    gather_cand_kernel<<<(NC + 7) / 8, 256, 0, s2>>>(candidates, W_tab);
    cudaEventRecord(evJoin, s2);

    // main: hops (compute/smem-bound; overlaps with cand gather)
    hops_kernel<<<B, HOP_THREADS, hops_smem>>>(H_w);

    // join, then single-wave gemm
    cudaStreamWaitEvent(0, evJoin, 0);
    gemm_kernel<<<NC / CT, GT, gemm_smem>>>(out);
}

// round 13
// speedup vs baseline: 1.1561x; 1.0621x over previous
#include <cuda_runtime.h>

#define B   128
#define M   200
#define S   20
#define D   128
#define NC  10000
#define CL  10
#define HOPS 3

// Scratch (no cudaMalloc allowed)
__device__ float g_m[B * M * D];      // 13.1 MB: memory encodings
__device__ float g_u[B * D];          // query state (b-major, hops input)
__device__ float g_uT[D * B];         // query state transposed (gemm A operand)
__device__ float g_cand[NC * D];      // candidate sums

// ---------------------------------------------------------------------------
// Gather primitives (R6 structure: warp per row, measured near LTS cap)
// ---------------------------------------------------------------------------
template <int N>
__device__ __forceinline__ void gather_row(const int* __restrict__ idxp,
                                           const float* __restrict__ tab,
                                           float* __restrict__ dst,
                                           int lane) {
    int myidx = (lane < N) ? idxp[lane] : 0;
    float4 acc = make_float4(0.f, 0.f, 0.f, 0.f);
#pragma unroll
    for (int s = 0; s < N; s++) {
        int idx = __shfl_sync(0xffffffffu, myidx, s);
        if (idx != 0) {
            float4 v = *(const float4*)(tab + (size_t)idx * D + lane * 4);
            acc.x += v.x; acc.y += v.y; acc.z += v.z; acc.w += v.w;
        }
    }
    *(float4*)(dst + lane * 4) = acc;
}

// Kernel 1a (main stream): story + query gathers (A table only)
#define SQ_ROWS (B * M + B)
__global__ void gather_sq_kernel(const int* __restrict__ stories,
                                 const int* __restrict__ queries,
                                 const float* __restrict__ A) {
    const int row  = (blockIdx.x * blockDim.x + threadIdx.x) >> 5;
    const int lane = threadIdx.x & 31;
    if (row >= SQ_ROWS) return;
    if (row < B * M) {
        gather_row<S>(stories + (size_t)row * S, A, g_m + (size_t)row * D, lane);
    } else {
        const int b = row - B * M;
        gather_row<S>(queries + (size_t)b * S, A, g_u + (size_t)b * D, lane);
    }
}

// Kernel 1b (side stream, AFTER sq-gather, overlapped with hops)
__global__ void gather_cand_kernel(const int* __restrict__ candidates,
                                   const float* __restrict__ W) {
    const int row  = (blockIdx.x * blockDim.x + threadIdx.x) >> 5;
    const int lane = threadIdx.x & 31;
    if (row >= NC) return;
    gather_row<CL>(candidates + (size_t)row * CL, W, g_cand + (size_t)row * D, lane);
}

// ---------------------------------------------------------------------------
// Kernel 2: 3 attention hops (unchanged from R12).
// ---------------------------------------------------------------------------
#define HW_PITCH 129
#define HOP_THREADS 256

__global__ void hops_kernel(const float* __restrict__ Hw) {
    extern __shared__ float smem[];
    float* sm_m   = smem;                        // M*D
    float* sm_h   = sm_m + M * D;                // D*HW_PITCH
    float* sm_u   = sm_h + D * HW_PITCH;         // D
    float* sm_dot = sm_u + D;                    // M
    float* sm_po  = sm_dot + M;                  // 256
    float* sm_ph  = sm_po + HOP_THREADS;         // 256
    float* sm_red = sm_ph + HOP_THREADS;         // 16

    const int b  = blockIdx.x;
    const int t  = threadIdx.x;
    const int warp = t >> 5, lane = t & 31;

    {
        const float4* gm4 = (const float4*)(g_m + (size_t)b * M * D);
        float4* sm4 = (float4*)sm_m;
        for (int i = t; i < M * D / 4; i += HOP_THREADS) sm4[i] = gm4[i];
        for (int i = t; i < D * D; i += HOP_THREADS) {
            int d = i >> 7, k = i & 127;
            sm_h[d * HW_PITCH + k] = Hw[i];
        }
        if (t < D) sm_u[t] = g_u[b * D + t];
    }
    __syncthreads();

    for (int hop = 0; hop < HOPS; hop++) {
        float ur[4];
#pragma unroll
        for (int i = 0; i < 4; i++) ur[i] = sm_u[lane + 32 * i];

        for (int mm = warp; mm < M; mm += HOP_THREADS / 32) {
            const float* row = sm_m + mm * D;
            float s = 0.f;
#pragma unroll
            for (int i = 0; i < 4; i++) s += row[lane + 32 * i] * ur[i];
#pragma unroll
            for (int off = 16; off; off >>= 1)
                s += __shfl_xor_sync(0xffffffffu, s, off);
            if (lane == 0) sm_dot[mm] = s;
        }
        __syncthreads();

        float v = (t < M) ? sm_dot[t] : -1e30f;
#pragma unroll
        for (int off = 16; off; off >>= 1)
            v = fmaxf(v, __shfl_xor_sync(0xffffffffu, v, off));
        if (lane == 0) sm_red[warp] = v;
        __syncthreads();
        if (t == 0) {
            float mx = sm_red[0];
#pragma unroll
            for (int w = 1; w < 8; w++) mx = fmaxf(mx, sm_red[w]);
            sm_red[8] = mx;
        }
        __syncthreads();
        const float mx = sm_red[8];

        float e = 0.f;
        if (t < M) { e = __expf(sm_dot[t] - mx); sm_dot[t] = e; }
        float sv = e;
#pragma unroll
        for (int off = 16; off; off >>= 1)
            sv += __shfl_xor_sync(0xffffffffu, sv, off);
        if (lane == 0) sm_red[warp] = sv;
        __syncthreads();
        if (t == 0) {
            float su = 0.f;
#pragma unroll
            for (int w = 0; w < 8; w++) su += sm_red[w];
            sm_red[9] = 1.f / su;
        }
        __syncthreads();
        const float inv = sm_red[9];

        {
            const int half = t >> 7;
            const int d    = t & 127;
            float o = 0.f;
            const int m0 = half * (M / 2), m1 = m0 + (M / 2);
            for (int mm = m0; mm < m1; mm++)
                o += sm_dot[mm] * sm_m[mm * D + d];
            sm_po[t] = o;

            float h = 0.f;
            const int k0 = half * (D / 2), k1 = k0 + (D / 2);
            const float* hr = sm_h + d * HW_PITCH;
#pragma unroll 8
            for (int k = k0; k < k1; k++) h += hr[k] * sm_u[k];
            sm_ph[t] = h;
        }
        __syncthreads();

        if (t < D) {
            float o = (sm_po[t] + sm_po[t + 128]) * inv;
            float h = sm_ph[t] + sm_ph[t + 128];
            sm_u[t] = tanhf(h + o);
        }
        __syncthreads();
    }
    if (t < D) g_uT[t * B + b] = sm_u[t];
}

// ---------------------------------------------------------------------------
// Kernel 3: logits = u @ cand^T. Single wave: 125 CTAs (10000 = 125 x 80),
// 640 threads (32 tb x 20 tc), per-thread 4b x 4c.
// C operand stays ROW-major in smem (no transpose; staging = coalesced float4
// memcpy). Thread's 4 c-rows are stride-20 interleaved: per-phase lane stride
// = 1 row = 132 floats = 4 banks -> LDS.128 conflict-free (banks 0,4,..,28).
// Microkernel: per k-chunk of 4, 8x LDS.128 then 64 FFMA (4x4x4 outer prod).
// ---------------------------------------------------------------------------
#define CT    80                // c-tile width
#define SUP   132               // su pitch floats (33 float4)
#define SCPC  132               // sc row pitch floats (33 float4), c-row-major
#define GT    640               // gemm threads (20 warps)

__global__ void __launch_bounds__(GT, 1) gemm_kernel(float* __restrict__ out) {
    extern __shared__ float sm[];
    float* su = sm;               // su[k*SUP + b]   k-major, 128 b
    float* sc = sm + D * SUP;     // sc[c*SCPC + k]  c-row-major, 80 c
    const int t = threadIdx.x;
    const int cbase = blockIdx.x * CT;

    // stage su: direct float4 copy of g_uT (row = k, 32 float4 per row)
    {
        const float4* src = (const float4*)g_uT;
        float4* dst = (float4*)su;
        for (int i = t; i < D * (B / 4); i += GT) {
            int row = i >> 5, col = i & 31;           // 32 f4 per row
            dst[row * (SUP / 4) + col] = src[row * (B / 4) + col];
        }
    }
    // stage sc: direct float4 copy of 80 cand rows (512B each), no transpose
    {
        const float4* src = (const float4*)(g_cand + (size_t)cbase * D);
        float4* dst = (float4*)sc;
        for (int i = t; i < CT * (D / 4); i += GT) {
            int row = i >> 5, col = i & 31;
            dst[row * (SCPC / 4) + col] = src[row * (D / 4) + col];
        }
    }
    __syncthreads();

    const int tc = t % 20, tb = t / 20;   // tb 0..31, tc 0..19
    const int b0 = tb * 4;
    // this thread's 4 c rows: tc, tc+20, tc+40, tc+60 (stride-20 interleave)
    float acc[4][4] = {};                 // [b][c-slot]

#pragma unroll
    for (int k = 0; k < D; k += 4) {
        float4 a[4], c[4];
#pragma unroll
        for (int q = 0; q < 4; q++)
            a[q] = *(const float4*)&su[(k + q) * SUP + b0];      // broadcast in phase
#pragma unroll
        for (int j = 0; j < 4; j++)
            c[j] = *(const float4*)&sc[(tc + 20 * j) * SCPC + k]; // conflict-free
#pragma unroll
        for (int j = 0; j < 4; j++) {
            acc[0][j] += a[0].x * c[j].x + a[1].x * c[j].y + a[2].x * c[j].z + a[3].x * c[j].w;
            acc[1][j] += a[0].y * c[j].x + a[1].y * c[j].y + a[2].y * c[j].z + a[3].y * c[j].w;
            acc[2][j] += a[0].z * c[j].x + a[1].z * c[j].y + a[2].z * c[j].z + a[3].z * c[j].w;
            acc[3][j] += a[0].w * c[j].x + a[1].w * c[j].y + a[2].w * c[j].z + a[3].w * c[j].w;
        }
    }

    // scalar stores; lanes with consecutive tc -> consecutive c -> coalesced
#pragma unroll
    for (int i = 0; i < 4; i++) {
        float* orow = out + (size_t)(b0 + i) * NC + cbase + tc;
#pragma unroll
        for (int j = 0; j < 4; j++) orow[20 * j] = acc[i][j];
    }
}

// ---------------------------------------------------------------------------
extern "C" void kernel_launch(void* const* d_in, const int* in_sizes, int n_in,
                              void* d_out, int out_size) {
    const int*   stories    = (const int*)d_in[0];
    const int*   queries    = (const int*)d_in[1];
    const int*   candidates = (const int*)d_in[2];
    const float* A_tab      = (const float*)d_in[3];
    const float* W_tab      = (const float*)d_in[4];
    const float* H_w        = (const float*)d_in[5];
    float*       out        = (float*)d_out;

    static cudaStream_t s2 = nullptr;
    static cudaEvent_t  evSq = nullptr, evJoin = nullptr;
    if (s2 == nullptr) {
        cudaStreamCreateWithFlags(&s2, cudaStreamNonBlocking);
        cudaEventCreateWithFlags(&evSq, cudaEventDisableTiming);
        cudaEventCreateWithFlags(&evJoin, cudaEventDisableTiming);
    }

    const int hops_smem = (M * D + D * HW_PITCH + D + M + 2 * HOP_THREADS + 16) * sizeof(float);
    const int gemm_smem = (D * SUP + CT * SCPC) * sizeof(float);   // ~109 KB
    cudaFuncSetAttribute(hops_kernel, cudaFuncAttributeMaxDynamicSharedMemorySize, hops_smem);
    cudaFuncSetAttribute(gemm_kernel, cudaFuncAttributeMaxDynamicSharedMemorySize, gemm_smem);

    // main: sq gather first (full LTS to itself)
    gather_sq_kernel<<<(SQ_ROWS + 7) / 8, 256>>>(stories, queries, A_tab);
    cudaEventRecord(evSq, 0);

    // side: cand gather AFTER sq gather, concurrent with hops
    cudaStreamWaitEvent(s2, evSq, 0);
    gather_cand_kernel<<<(NC + 7) / 8, 256, 0, s2>>>(candidates, W_tab);
    cudaEventRecord(evJoin, s2);

    // main: hops (compute/smem-bound; overlaps with cand gather)
    hops_kernel<<<B, HOP_THREADS, hops_smem>>>(H_w);

    // join, then single-wave gemm
    cudaStreamWaitEvent(0, evJoin, 0);
    gemm_kernel<<<NC / CT, GT, gemm_smem>>>(out);
}